// round 2
// baseline (speedup 1.0000x reference)
#include <cuda_runtime.h>
#include <math.h>

// ---------------- problem constants ----------------
#define BB 4
#define HH 256
#define WW 256
#define HWSZ (HH*WW)

// ---------------- scratch buffers ----------------
__device__ float g_cat [(size_t)BB*128*HWSZ];  // f1 (ch0..63) | f2 (ch64..127)
__device__ float g_x128[(size_t)BB*128*HWSZ];  // fc1 output
__device__ float g_corr[(size_t)BB*113*HWSZ];  // feat (0..63) | lc (64..112)
__device__ float g_f1s [(size_t)BB*64*HWSZ];   // blurred f1
__device__ float g_tmp [(size_t)BB*64*HWSZ];   // blur horizontal pass scratch
__device__ float g_x64 [(size_t)BB*64*HWSZ];
__device__ float g_x32 [(size_t)BB*32*HWSZ];
__device__ float g_x16 [(size_t)BB*16*HWSZ];
__device__ float g_head[(size_t)BB*2*HWSZ];
__device__ float g_lcsum[BB];

// gaussian 1d kernel (sigma=1.5, size 7), normalized
__constant__ float GK[7] = {0.03663285f, 0.11128102f, 0.21674443f, 0.27068263f,
                            0.21674443f, 0.11128102f, 0.03663285f};

// ---------------- generic 3x3 conv, zero pad = dilation ----------------
// tile: 8 rows x 64 cols, 128 threads, each thread 4 px x 16 out-channels
#define C_TH 8
#define C_TW 64
#define C_NT 128
#define C_CO 16
#define C_PX 4

template<int DIL>
__global__ void conv3x3_kernel(const float* __restrict__ in, int Cin, int CinS, int cinOff,
                               const float* __restrict__ wgt, const float* __restrict__ bias,
                               float* __restrict__ out, int Cout, int CoutS, int coutOff)
{
    constexpr int TLW = C_TW + 2*DIL;
    constexpr int TLH = C_TH + 2*DIL;
    __shared__ float s_in[TLH*TLW];
    __shared__ float s_w[C_CO*9];

    const int nCb = (Cout + C_CO - 1)/C_CO;
    const int b  = blockIdx.z / nCb;
    const int cb = (blockIdx.z % nCb)*C_CO;
    const int y0g = blockIdx.y*C_TH;
    const int x0g = blockIdx.x*C_TW;
    const int tid = threadIdx.x;
    const int ty  = tid >> 4;
    const int x0  = (tid & 15)*C_PX;

    float acc[C_CO][C_PX];
#pragma unroll
    for (int co=0;co<C_CO;co++)
#pragma unroll
        for (int i=0;i<C_PX;i++) acc[co][i]=0.f;

    for (int ci=0; ci<Cin; ci++) {
        const float* ip = in + ((size_t)(b*CinS + cinOff + ci))*HWSZ;
        for (int idx=tid; idx<TLH*TLW; idx+=C_NT) {
            int r = idx / TLW, c = idx % TLW;
            int gy = y0g + r - DIL, gx = x0g + c - DIL;
            float v = 0.f;
            if (gy>=0 && gy<HH && gx>=0 && gx<WW) v = ip[gy*WW+gx];
            s_in[idx] = v;
        }
        for (int idx=tid; idx<C_CO*9; idx+=C_NT) {
            int co = idx/9, k = idx%9;
            int gco = cb + co;
            s_w[idx] = (gco < Cout) ? wgt[((size_t)gco*Cin + ci)*9 + k] : 0.f;
        }
        __syncthreads();
#pragma unroll
        for (int ky=0; ky<3; ky++) {
#pragma unroll
            for (int kx=0; kx<3; kx++) {
                const int base = (ty + ky*DIL)*TLW + x0 + kx*DIL;
                float v[C_PX];
#pragma unroll
                for (int i=0;i<C_PX;i++) v[i] = s_in[base+i];
                const int k = ky*3+kx;
#pragma unroll
                for (int co=0; co<C_CO; co++) {
                    float wv = s_w[co*9 + k];
#pragma unroll
                    for (int i=0;i<C_PX;i++) acc[co][i] += wv*v[i];
                }
            }
        }
        __syncthreads();
    }
#pragma unroll
    for (int co=0; co<C_CO; co++) {
        int gco = cb + co;
        if (gco >= Cout) break;
        float bv = bias ? bias[gco] : 0.f;
        float* op = out + ((size_t)(b*CoutS + coutOff + gco))*HWSZ + (y0g+ty)*WW + x0g + x0;
#pragma unroll
        for (int i=0;i<C_PX;i++) op[i] = acc[co][i] + bv;
    }
}

// ---------------- instance norm + leaky relu (in place) ----------------
__global__ void instnorm_lrelu_kernel(float* __restrict__ x, const float* __restrict__ gamma,
                                      const float* __restrict__ beta, int C)
{
    const int bc = blockIdx.x;
    float* p = x + (size_t)bc*HWSZ;
    const int tid = threadIdx.x;
    float s = 0.f, s2 = 0.f;
    for (int i=tid; i<HWSZ; i+=256) { float v = p[i]; s += v; s2 += v*v; }
    __shared__ float rs[256], rq[256];
    rs[tid]=s; rq[tid]=s2; __syncthreads();
    for (int off=128; off>0; off>>=1) {
        if (tid<off) { rs[tid]+=rs[tid+off]; rq[tid]+=rq[tid+off]; }
        __syncthreads();
    }
    const float mu  = rs[0]*(1.f/HWSZ);
    const float var = rq[0]*(1.f/HWSZ) - mu*mu;
    const float inv = rsqrtf(var + 1e-5f);
    const int c = bc % C;
    const float ga = gamma[c], be = beta[c];
    for (int i=tid; i<HWSZ; i+=256) {
        float v = (p[i]-mu)*inv*ga + be;
        p[i] = (v >= 0.f) ? v : 0.2f*v;
    }
}

// ---------------- separable gaussian blur, replicate padding ----------------
__global__ void blur_h_kernel(const float* __restrict__ in, int CinS, int cinOff,
                              float* __restrict__ out, int C, int n)
{
    int idx = blockIdx.x*blockDim.x + threadIdx.x;
    if (idx >= n) return;
    int x = idx % WW;
    int y = (idx / WW) % HH;
    int bc = idx / HWSZ;
    int b = bc / C, c = bc % C;
    const float* ip = in + ((size_t)(b*CinS + cinOff + c))*HWSZ + y*WW;
    float s = 0.f;
#pragma unroll
    for (int t=0; t<7; t++) {
        int xx = x + t - 3;
        xx = min(max(xx,0), WW-1);
        s += GK[t]*ip[xx];
    }
    out[(size_t)bc*HWSZ + y*WW + x] = s;
}

__global__ void blur_v_kernel(const float* __restrict__ in, float* __restrict__ out, int n)
{
    int idx = blockIdx.x*blockDim.x + threadIdx.x;
    if (idx >= n) return;
    int x = idx % WW;
    int y = (idx / WW) % HH;
    int bc = idx / HWSZ;
    const float* ip = in + (size_t)bc*HWSZ;
    float s = 0.f;
#pragma unroll
    for (int t=0; t<7; t++) {
        int yy = y + t - 3;
        yy = min(max(yy,0), HH-1);
        s += GK[t]*ip[yy*WW + x];
    }
    out[(size_t)bc*HWSZ + y*WW + x] = s;
}

// ---------------- local correlation ----------------
// lc[b, i*7+j, y, x] = mean_c (f2[c,y,x] - zeropad3(f1s)[c, y+i, x+j])^2
__global__ void corr_kernel(const float* __restrict__ f1s, const float* __restrict__ f2base,
                            float* __restrict__ out, float* __restrict__ lcsum)
{
    __shared__ float s1[22*22];
    __shared__ float red[256];
    const int bx = blockIdx.x, by = blockIdx.y, b = blockIdx.z;
    const int tid = threadIdx.x;
    const int ty = tid >> 4, tx = tid & 15;
    const int gy = by*16 + ty, gx = bx*16 + tx;

    float acc[49];
#pragma unroll
    for (int k=0;k<49;k++) acc[k]=0.f;

    for (int c=0; c<64; c++) {
        const float* p1 = f1s   + ((size_t)(b*64  + c))*HWSZ;
        const float* p2 = f2base + ((size_t)(b*128 + 64 + c))*HWSZ;
        for (int idx=tid; idx<22*22; idx+=256) {
            int r = idx/22, cc = idx%22;
            int yy = by*16 + r - 3, xx = bx*16 + cc - 3;
            s1[idx] = (yy>=0 && yy<HH && xx>=0 && xx<WW) ? p1[yy*WW+xx] : 0.f;
        }
        __syncthreads();
        const float v2 = p2[gy*WW + gx];
#pragma unroll
        for (int i=0;i<7;i++) {
#pragma unroll
            for (int j=0;j<7;j++) {
                float d = v2 - s1[(ty+i)*22 + tx+j];
                acc[i*7+j] += d*d;
            }
        }
        __syncthreads();
    }
    float tsum = 0.f;
#pragma unroll
    for (int k=0;k<49;k++) {
        float lc = acc[k]*(1.f/64.f);
        out[((size_t)(b*113 + 64 + k))*HWSZ + gy*WW + gx] = lc;
        tsum += lc;
    }
    red[tid] = tsum; __syncthreads();
    for (int off=128; off>0; off>>=1) {
        if (tid<off) red[tid] += red[tid+off];
        __syncthreads();
    }
    if (tid==0) atomicAdd(&lcsum[b], red[0]);
}

__global__ void zero_lcsum_kernel(float* lcsum)
{
    if (threadIdx.x < BB) lcsum[threadIdx.x] = 0.f;
}

__global__ void lcnorm_kernel(float* __restrict__ corr, const float* __restrict__ lcsum, int n)
{
    int idx = blockIdx.x*blockDim.x + threadIdx.x;
    if (idx >= n) return;
    int b = idx / (49*HWSZ);
    int r = idx - b*(49*HWSZ);
    float mean = lcsum[b]*(1.f/(49.f*HWSZ));
    float s = 1.f/(mean + 1e-6f);
    corr[((size_t)b*113 + 64)*HWSZ + r] *= s;
}

// ---------------- host side ----------------
static void launch_conv(int dil, const float* in, int Cin, int CinS, int cinOff,
                        const float* w, const float* bias,
                        float* out, int Cout, int CoutS, int coutOff)
{
    int nCb = (Cout + C_CO - 1)/C_CO;
    dim3 grid(WW/C_TW, HH/C_TH, BB*nCb);
    if (dil == 1)
        conv3x3_kernel<1><<<grid, C_NT>>>(in,Cin,CinS,cinOff,w,bias,out,Cout,CoutS,coutOff);
    else if (dil == 2)
        conv3x3_kernel<2><<<grid, C_NT>>>(in,Cin,CinS,cinOff,w,bias,out,Cout,CoutS,coutOff);
    else
        conv3x3_kernel<4><<<grid, C_NT>>>(in,Cin,CinS,cinOff,w,bias,out,Cout,CoutS,coutOff);
}

extern "C" void kernel_launch(void* const* d_in, const int* in_sizes, int n_in,
                              void* d_out, int out_size)
{
    const float* feat1  = (const float*)d_in[0];
    const float* feat2  = (const float*)d_in[1];
    const float* pre_w  = (const float*)d_in[2];
    const float* pre_b  = (const float*)d_in[3];
    const float* fc1_w  = (const float*)d_in[4];
    const float* fc1_g  = (const float*)d_in[5];
    const float* fc1_be = (const float*)d_in[6];
    const float* fc2_w  = (const float*)d_in[7];
    const float* fc2_b  = (const float*)d_in[8];
    const float* e1_w   = (const float*)d_in[9];
    const float* e1_g   = (const float*)d_in[10];
    const float* e1_be  = (const float*)d_in[11];
    const float* e2_w   = (const float*)d_in[12];
    const float* e2_g   = (const float*)d_in[13];
    const float* e2_be  = (const float*)d_in[14];
    const float* e3_w   = (const float*)d_in[15];
    const float* e3_g   = (const float*)d_in[16];
    const float* e3_be  = (const float*)d_in[17];
    const float* head_w = (const float*)d_in[18];
    const float* head_b = (const float*)d_in[19];
    float* out = (float*)d_out;

    float *cat_, *x128, *corr_, *f1s, *tmp_, *x64, *x32, *x16, *head_, *lcsum;
    cudaGetSymbolAddress((void**)&cat_,  g_cat);
    cudaGetSymbolAddress((void**)&x128,  g_x128);
    cudaGetSymbolAddress((void**)&corr_, g_corr);
    cudaGetSymbolAddress((void**)&f1s,   g_f1s);
    cudaGetSymbolAddress((void**)&tmp_,  g_tmp);
    cudaGetSymbolAddress((void**)&x64,   g_x64);
    cudaGetSymbolAddress((void**)&x32,   g_x32);
    cudaGetSymbolAddress((void**)&x16,   g_x16);
    cudaGetSymbolAddress((void**)&head_, g_head);
    cudaGetSymbolAddress((void**)&lcsum, g_lcsum);

    // preprocessor (shared weights) -> concat buffer
    launch_conv(1, feat1, 64, 64, 0, pre_w, pre_b, cat_, 64, 128, 0);
    launch_conv(1, feat2, 64, 64, 0, pre_w, pre_b, cat_, 64, 128, 64);

    // featcompressor layer1 + IN + lrelu
    launch_conv(1, cat_, 128, 128, 0, fc1_w, nullptr, x128, 128, 128, 0);
    instnorm_lrelu_kernel<<<BB*128, 256>>>(x128, fc1_g, fc1_be, 128);

    // featcompressor layer2 -> corr channels 0..63
    launch_conv(1, x128, 128, 128, 0, fc2_w, fc2_b, corr_, 64, 113, 0);

    // gaussian blur of f1 (replicate pad, separable)
    {
        int n = BB*64*HWSZ;
        blur_h_kernel<<<(n+255)/256, 256>>>(cat_, 128, 0, tmp_, 64, n);
        blur_v_kernel<<<(n+255)/256, 256>>>(tmp_, f1s, n);
    }

    // local correlation -> corr channels 64..112, then normalize by batch mean
    zero_lcsum_kernel<<<1, 32>>>(lcsum);
    corr_kernel<<<dim3(WW/16, HH/16, BB), 256>>>(f1s, cat_, corr_, lcsum);
    {
        int n = BB*49*HWSZ;
        lcnorm_kernel<<<(n+255)/256, 256>>>(corr_, lcsum, n);
    }

    // estimator stack
    launch_conv(1, corr_, 113, 113, 0, e1_w, nullptr, x64, 64, 64, 0);
    instnorm_lrelu_kernel<<<BB*64, 256>>>(x64, e1_g, e1_be, 64);

    launch_conv(2, x64, 64, 64, 0, e2_w, nullptr, x32, 32, 32, 0);
    instnorm_lrelu_kernel<<<BB*32, 256>>>(x32, e2_g, e2_be, 32);

    launch_conv(4, x32, 32, 32, 0, e3_w, nullptr, x16, 16, 16, 0);
    instnorm_lrelu_kernel<<<BB*16, 256>>>(x16, e3_g, e3_be, 16);

    // flow head
    launch_conv(1, x16, 16, 16, 0, head_w, head_b, head_, 2, 2, 0);

    // final blur -> output
    {
        int n = BB*2*HWSZ;
        blur_h_kernel<<<(n+255)/256, 256>>>(head_, 2, 0, tmp_, 2, n);
        blur_v_kernel<<<(n+255)/256, 256>>>(tmp_, out, n);
    }
}

// round 3
// speedup vs baseline: 1.4493x; 1.4493x over previous
#include <cuda_runtime.h>
#include <math.h>

// ---------------- problem constants ----------------
#define BB 4
#define HH 256
#define WW 256
#define HWSZ (HH*WW)

typedef unsigned long long ull;

// ---------------- scratch buffers ----------------
__device__ float g_cat [(size_t)BB*128*HWSZ];  // f1 (ch0..63) | f2 (ch64..127)
__device__ float g_x128[(size_t)BB*128*HWSZ];  // fc1 output
__device__ float g_corr[(size_t)BB*113*HWSZ];  // feat (0..63) | lc (64..112)
__device__ float g_f1s [(size_t)BB*64*HWSZ];   // blurred f1
__device__ float g_tmp [(size_t)BB*64*HWSZ];   // blur horizontal pass scratch
__device__ float g_x64 [(size_t)BB*64*HWSZ];
__device__ float g_x32 [(size_t)BB*32*HWSZ];
__device__ float g_x16 [(size_t)BB*16*HWSZ];
__device__ float g_head[(size_t)BB*2*HWSZ];
__device__ float g_lcsum[BB];

// gaussian 1d kernel (sigma=1.5, size 7), normalized
__constant__ float GK[7] = {0.03663285f, 0.11128102f, 0.21674443f, 0.27068263f,
                            0.21674443f, 0.11128102f, 0.03663285f};

// ---------------- f32x2 packed helpers ----------------
__device__ __forceinline__ ull pk2(float lo, float hi) {
    ull r; asm("mov.b64 %0, {%1, %2};" : "=l"(r) : "f"(lo), "f"(hi)); return r;
}
__device__ __forceinline__ void fma2(ull& d, ull a, ull b) {
    asm("fma.rn.f32x2 %0, %1, %2, %0;" : "+l"(d) : "l"(a), "l"(b));
}
__device__ __forceinline__ ull add2(ull a, ull b) {
    ull r; asm("add.rn.f32x2 %0, %1, %2;" : "=l"(r) : "l"(a), "l"(b)); return r;
}

// ---------------- 3x3 conv, zero pad = dilation, FFMA2 inner loop ----------
// tile 16 rows x 64 cols, 128 threads; each thread: 8 out-channels x 8 px
#define C_NT 128
#define C_TH 16
#define C_TW 64
#define C_CO 8
// pixels per thread = 8 (4 f32x2 pairs)

template<int DIL>
__global__ __launch_bounds__(C_NT, 3)
void conv3x3_kernel(const float* __restrict__ in, int Cin, int CinS, int cinOff,
                    const float* __restrict__ wgt, const float* __restrict__ bias,
                    float* __restrict__ out, int Cout, int CoutS, int coutOff)
{
    constexpr int TLW = C_TW + 2*DIL;
    constexpr int TLH = C_TH + 2*DIL;
    constexpr int NE  = (DIL==1) ? 5 : (DIL==2) ? 6 : 8;   // even-aligned pairs per row window
    __shared__ __align__(16) float s_in[2][TLH*TLW];
    __shared__ __align__(16) ull   s_w2[2][C_CO*9];

    const int cb   = blockIdx.x * C_CO;          // out-channel block (fastest -> L2 reuse)
    const int tile = blockIdx.y;
    const int x0g  = (tile & 3) * C_TW;
    const int y0g  = (tile >> 2) * C_TH;
    const int b    = blockIdx.z;
    const int tid  = threadIdx.x;
    const int ty   = tid >> 3;          // 0..15
    const int xo   = (tid & 7) * 8;     // 0..56, 32B aligned

    ull acc[C_CO][4];
#pragma unroll
    for (int co=0;co<C_CO;co++)
#pragma unroll
        for (int p=0;p<4;p++) acc[co][p] = 0ull;

    const bool interior = (x0g >= DIL) && (x0g + C_TW + DIL <= WW) &&
                          (y0g >= DIL) && (y0g + C_TH + DIL <= HH);

    for (int ci0 = 0; ci0 < Cin; ci0 += 2) {
        // ---- fill input tiles (2 channels) ----
#pragma unroll
        for (int cc = 0; cc < 2; cc++) {
            const int ci = ci0 + cc;
            const float* ip = in + ((size_t)(b*CinS + cinOff + ci))*HWSZ;
            if (ci < Cin && interior) {
                for (int idx = tid; idx < TLH*TLW; idx += C_NT) {
                    int r = idx / TLW, c = idx - r*TLW;
                    s_in[cc][idx] = ip[(y0g + r - DIL)*WW + (x0g + c - DIL)];
                }
            } else {
                const bool cv = (ci < Cin);
                for (int idx = tid; idx < TLH*TLW; idx += C_NT) {
                    int r = idx / TLW, c = idx - r*TLW;
                    int gy = y0g + r - DIL, gx = x0g + c - DIL;
                    float v = 0.f;
                    if (cv && gy >= 0 && gy < HH && gx >= 0 && gx < WW) v = ip[gy*WW + gx];
                    s_in[cc][idx] = v;
                }
            }
        }
        // ---- fill duplicated weight pairs ----
        for (int idx = tid; idx < 2*C_CO*9; idx += C_NT) {
            int cc = idx / (C_CO*9);
            int t  = idx - cc*(C_CO*9);
            int co = t / 9, k = t - co*9;
            int gci = ci0 + cc, gco = cb + co;
            float w = (gci < Cin && gco < Cout) ? wgt[((size_t)gco*Cin + gci)*9 + k] : 0.f;
            s_w2[cc][t] = pk2(w, w);
        }
        __syncthreads();

        // ---- compute ----
#pragma unroll
        for (int cc = 0; cc < 2; cc++) {
#pragma unroll
            for (int ky = 0; ky < 3; ky++) {
                const float* rowp = &s_in[cc][(ty + ky*DIL)*TLW + xo];
                ull E[NE];
#pragma unroll
                for (int i = 0; i < NE; i++)
                    E[i] = *(const ull*)(rowp + 2*i);   // 8B aligned LDS.64
                ull O[4];
                if (DIL == 1) {
#pragma unroll
                    for (int i = 0; i < 4; i++)
                        O[i] = pk2(rowp[2*i+1], rowp[2*i+2]);
                }
#pragma unroll
                for (int kx = 0; kx < 3; kx++) {
                    ull vv[4];
                    if (DIL == 1) {
                        if (kx == 0)      { vv[0]=E[0]; vv[1]=E[1]; vv[2]=E[2]; vv[3]=E[3]; }
                        else if (kx == 1) { vv[0]=O[0]; vv[1]=O[1]; vv[2]=O[2]; vv[3]=O[3]; }
                        else              { vv[0]=E[1]; vv[1]=E[2]; vv[2]=E[3]; vv[3]=E[4]; }
                    } else {
                        const int base = kx*(DIL/2);
#pragma unroll
                        for (int p = 0; p < 4; p++) vv[p] = E[base + p];
                    }
#pragma unroll
                    for (int co = 0; co < C_CO; co++) {
                        ull w = s_w2[cc][co*9 + ky*3 + kx];
#pragma unroll
                        for (int p = 0; p < 4; p++) fma2(acc[co][p], w, vv[p]);
                    }
                }
            }
        }
        __syncthreads();
    }

    // ---- epilogue ----
#pragma unroll
    for (int co = 0; co < C_CO; co++) {
        int gco = cb + co;
        if (gco >= Cout) break;
        float bv = bias ? bias[gco] : 0.f;
        ull bv2 = pk2(bv, bv);
        float* op = out + ((size_t)(b*CoutS + coutOff + gco))*HWSZ + (y0g + ty)*WW + x0g + xo;
#pragma unroll
        for (int p = 0; p < 4; p++) {
            ull r = add2(acc[co][p], bv2);
            *(ull*)(op + 2*p) = r;
        }
    }
}

// ---------------- instance norm + leaky relu (in place, float4) ----------
__global__ void instnorm_lrelu_kernel(float* __restrict__ x, const float* __restrict__ gamma,
                                      const float* __restrict__ beta, int C)
{
    const int bc = blockIdx.x;
    float4* p = (float4*)(x + (size_t)bc*HWSZ);
    const int N4 = HWSZ/4;
    const int tid = threadIdx.x;
    float s = 0.f, s2 = 0.f;
    for (int i = tid; i < N4; i += 256) {
        float4 v = p[i];
        s  += v.x + v.y + v.z + v.w;
        s2 += v.x*v.x + v.y*v.y + v.z*v.z + v.w*v.w;
    }
    __shared__ float rs[256], rq[256];
    rs[tid] = s; rq[tid] = s2; __syncthreads();
    for (int off = 128; off > 0; off >>= 1) {
        if (tid < off) { rs[tid] += rs[tid+off]; rq[tid] += rq[tid+off]; }
        __syncthreads();
    }
    const float mu  = rs[0]*(1.f/HWSZ);
    const float var = rq[0]*(1.f/HWSZ) - mu*mu;
    const float inv = rsqrtf(var + 1e-5f);
    const int c = bc % C;
    const float ga = gamma[c]*inv, be = beta[c];
    for (int i = tid; i < N4; i += 256) {
        float4 v = p[i];
        v.x = (v.x-mu)*ga + be; v.x = (v.x >= 0.f) ? v.x : 0.2f*v.x;
        v.y = (v.y-mu)*ga + be; v.y = (v.y >= 0.f) ? v.y : 0.2f*v.y;
        v.z = (v.z-mu)*ga + be; v.z = (v.z >= 0.f) ? v.z : 0.2f*v.z;
        v.w = (v.w-mu)*ga + be; v.w = (v.w >= 0.f) ? v.w : 0.2f*v.w;
        p[i] = v;
    }
}

// ---------------- separable gaussian blur, replicate padding ------------
__global__ void blur_h_kernel(const float* __restrict__ in, int CinS, int cinOff,
                              float* __restrict__ out, int C, int n)
{
    int idx = blockIdx.x*blockDim.x + threadIdx.x;
    if (idx >= n) return;
    int x = idx % WW;
    int y = (idx / WW) % HH;
    int bc = idx / HWSZ;
    int b = bc / C, c = bc % C;
    const float* ip = in + ((size_t)(b*CinS + cinOff + c))*HWSZ + y*WW;
    float s = 0.f;
#pragma unroll
    for (int t = 0; t < 7; t++) {
        int xx = x + t - 3;
        xx = min(max(xx, 0), WW-1);
        s += GK[t]*ip[xx];
    }
    out[(size_t)bc*HWSZ + y*WW + x] = s;
}

__global__ void blur_v_kernel(const float* __restrict__ in, float* __restrict__ out, int n)
{
    int idx = blockIdx.x*blockDim.x + threadIdx.x;
    if (idx >= n) return;
    int x = idx % WW;
    int y = (idx / WW) % HH;
    int bc = idx / HWSZ;
    const float* ip = in + (size_t)bc*HWSZ;
    float s = 0.f;
#pragma unroll
    for (int t = 0; t < 7; t++) {
        int yy = y + t - 3;
        yy = min(max(yy, 0), HH-1);
        s += GK[t]*ip[yy*WW + x];
    }
    out[(size_t)bc*HWSZ + y*WW + x] = s;
}

// ---------------- local correlation ----------------
__global__ void corr_kernel(const float* __restrict__ f1s, const float* __restrict__ f2base,
                            float* __restrict__ out, float* __restrict__ lcsum)
{
    __shared__ float s1[22*22];
    __shared__ float red[256];
    const int bx = blockIdx.x, by = blockIdx.y, b = blockIdx.z;
    const int tid = threadIdx.x;
    const int ty = tid >> 4, tx = tid & 15;
    const int gy = by*16 + ty, gx = bx*16 + tx;

    float acc[49];
#pragma unroll
    for (int k = 0; k < 49; k++) acc[k] = 0.f;

    for (int c = 0; c < 64; c++) {
        const float* p1 = f1s    + ((size_t)(b*64  + c))*HWSZ;
        const float* p2 = f2base + ((size_t)(b*128 + 64 + c))*HWSZ;
        for (int idx = tid; idx < 22*22; idx += 256) {
            int r = idx/22, cc = idx%22;
            int yy = by*16 + r - 3, xx = bx*16 + cc - 3;
            s1[idx] = (yy >= 0 && yy < HH && xx >= 0 && xx < WW) ? p1[yy*WW+xx] : 0.f;
        }
        __syncthreads();
        const float v2 = p2[gy*WW + gx];
#pragma unroll
        for (int i = 0; i < 7; i++) {
#pragma unroll
            for (int j = 0; j < 7; j++) {
                float d = v2 - s1[(ty+i)*22 + tx+j];
                acc[i*7+j] += d*d;
            }
        }
        __syncthreads();
    }
    float tsum = 0.f;
#pragma unroll
    for (int k = 0; k < 49; k++) {
        float lc = acc[k]*(1.f/64.f);
        out[((size_t)(b*113 + 64 + k))*HWSZ + gy*WW + gx] = lc;
        tsum += lc;
    }
    red[tid] = tsum; __syncthreads();
    for (int off = 128; off > 0; off >>= 1) {
        if (tid < off) red[tid] += red[tid+off];
        __syncthreads();
    }
    if (tid == 0) atomicAdd(&lcsum[b], red[0]);
}

__global__ void zero_lcsum_kernel(float* lcsum)
{
    if (threadIdx.x < BB) lcsum[threadIdx.x] = 0.f;
}

__global__ void lcnorm_kernel(float* __restrict__ corr, const float* __restrict__ lcsum, int n)
{
    int idx = blockIdx.x*blockDim.x + threadIdx.x;
    if (idx >= n) return;
    int b = idx / (49*HWSZ);
    int r = idx - b*(49*HWSZ);
    float mean = lcsum[b]*(1.f/(49.f*HWSZ));
    float s = 1.f/(mean + 1e-6f);
    corr[((size_t)b*113 + 64)*HWSZ + r] *= s;
}

// ---------------- host side ----------------
static void launch_conv(int dil, const float* in, int Cin, int CinS, int cinOff,
                        const float* w, const float* bias,
                        float* out, int Cout, int CoutS, int coutOff)
{
    int nCb = (Cout + C_CO - 1)/C_CO;
    dim3 grid(nCb, (WW/C_TW)*(HH/C_TH), BB);
    if (dil == 1)
        conv3x3_kernel<1><<<grid, C_NT>>>(in,Cin,CinS,cinOff,w,bias,out,Cout,CoutS,coutOff);
    else if (dil == 2)
        conv3x3_kernel<2><<<grid, C_NT>>>(in,Cin,CinS,cinOff,w,bias,out,Cout,CoutS,coutOff);
    else
        conv3x3_kernel<4><<<grid, C_NT>>>(in,Cin,CinS,cinOff,w,bias,out,Cout,CoutS,coutOff);
}

extern "C" void kernel_launch(void* const* d_in, const int* in_sizes, int n_in,
                              void* d_out, int out_size)
{
    const float* feat1  = (const float*)d_in[0];
    const float* feat2  = (const float*)d_in[1];
    const float* pre_w  = (const float*)d_in[2];
    const float* pre_b  = (const float*)d_in[3];
    const float* fc1_w  = (const float*)d_in[4];
    const float* fc1_g  = (const float*)d_in[5];
    const float* fc1_be = (const float*)d_in[6];
    const float* fc2_w  = (const float*)d_in[7];
    const float* fc2_b  = (const float*)d_in[8];
    const float* e1_w   = (const float*)d_in[9];
    const float* e1_g   = (const float*)d_in[10];
    const float* e1_be  = (const float*)d_in[11];
    const float* e2_w   = (const float*)d_in[12];
    const float* e2_g   = (const float*)d_in[13];
    const float* e2_be  = (const float*)d_in[14];
    const float* e3_w   = (const float*)d_in[15];
    const float* e3_g   = (const float*)d_in[16];
    const float* e3_be  = (const float*)d_in[17];
    const float* head_w = (const float*)d_in[18];
    const float* head_b = (const float*)d_in[19];
    float* out = (float*)d_out;

    float *cat_, *x128, *corr_, *f1s, *tmp_, *x64, *x32, *x16, *head_, *lcsum;
    cudaGetSymbolAddress((void**)&cat_,  g_cat);
    cudaGetSymbolAddress((void**)&x128,  g_x128);
    cudaGetSymbolAddress((void**)&corr_, g_corr);
    cudaGetSymbolAddress((void**)&f1s,   g_f1s);
    cudaGetSymbolAddress((void**)&tmp_,  g_tmp);
    cudaGetSymbolAddress((void**)&x64,   g_x64);
    cudaGetSymbolAddress((void**)&x32,   g_x32);
    cudaGetSymbolAddress((void**)&x16,   g_x16);
    cudaGetSymbolAddress((void**)&head_, g_head);
    cudaGetSymbolAddress((void**)&lcsum, g_lcsum);

    // preprocessor (shared weights) -> concat buffer
    launch_conv(1, feat1, 64, 64, 0, pre_w, pre_b, cat_, 64, 128, 0);
    launch_conv(1, feat2, 64, 64, 0, pre_w, pre_b, cat_, 64, 128, 64);

    // featcompressor layer1 + IN + lrelu
    launch_conv(1, cat_, 128, 128, 0, fc1_w, nullptr, x128, 128, 128, 0);
    instnorm_lrelu_kernel<<<BB*128, 256>>>(x128, fc1_g, fc1_be, 128);

    // featcompressor layer2 -> corr channels 0..63
    launch_conv(1, x128, 128, 128, 0, fc2_w, fc2_b, corr_, 64, 113, 0);

    // gaussian blur of f1 (replicate pad, separable)
    {
        int n = BB*64*HWSZ;
        blur_h_kernel<<<(n+255)/256, 256>>>(cat_, 128, 0, tmp_, 64, n);
        blur_v_kernel<<<(n+255)/256, 256>>>(tmp_, f1s, n);
    }

    // local correlation -> corr channels 64..112, then normalize by batch mean
    zero_lcsum_kernel<<<1, 32>>>(lcsum);
    corr_kernel<<<dim3(WW/16, HH/16, BB), 256>>>(f1s, cat_, corr_, lcsum);
    {
        int n = BB*49*HWSZ;
        lcnorm_kernel<<<(n+255)/256, 256>>>(corr_, lcsum, n);
    }

    // estimator stack
    launch_conv(1, corr_, 113, 113, 0, e1_w, nullptr, x64, 64, 64, 0);
    instnorm_lrelu_kernel<<<BB*64, 256>>>(x64, e1_g, e1_be, 64);

    launch_conv(2, x64, 64, 64, 0, e2_w, nullptr, x32, 32, 32, 0);
    instnorm_lrelu_kernel<<<BB*32, 256>>>(x32, e2_g, e2_be, 32);

    launch_conv(4, x32, 32, 32, 0, e3_w, nullptr, x16, 16, 16, 0);
    instnorm_lrelu_kernel<<<BB*16, 256>>>(x16, e3_g, e3_be, 16);

    // flow head
    launch_conv(1, x16, 16, 16, 0, head_w, head_b, head_, 2, 2, 0);

    // final blur -> output
    {
        int n = BB*2*HWSZ;
        blur_h_kernel<<<(n+255)/256, 256>>>(head_, 2, 0, tmp_, 2, n);
        blur_v_kernel<<<(n+255)/256, 256>>>(tmp_, out, n);
    }
}

// round 4
// speedup vs baseline: 4.7470x; 3.2754x over previous
#include <cuda_runtime.h>
#include <math.h>

// ---------------- problem constants ----------------
#define BB 4
#define HH 256
#define WW 256
#define HWSZ (HH*WW)

typedef unsigned long long ull;

// ---------------- scratch buffers ----------------
__device__ float g_cat [(size_t)BB*128*HWSZ];  // f1 (ch0..63) | f2 (ch64..127)
__device__ float g_x128[(size_t)BB*128*HWSZ];  // fc1 output
__device__ float g_corr[(size_t)BB*128*HWSZ];  // feat (0..63) | lc (64..112) | zero pad (113..127)
__device__ float g_f1s [(size_t)BB*64*HWSZ];   // blurred f1
__device__ float g_tmp [(size_t)BB*64*HWSZ];   // blur horizontal pass scratch
__device__ float g_x64 [(size_t)BB*64*HWSZ];
__device__ float g_x32 [(size_t)BB*32*HWSZ];
__device__ float g_x16 [(size_t)BB*16*HWSZ];
__device__ float g_head[(size_t)BB*2*HWSZ];
__device__ float g_lcsum[BB];
// prepped (reordered + tf32-rounded, ci-padded) weights
__device__ float g_wp[36864 + 147456 + 73728 + 73728 + 18432 + 4608];

// gaussian 1d kernel (sigma=1.5, size 7)
__constant__ float GK[7] = {0.03663285f, 0.11128102f, 0.21674443f, 0.27068263f,
                            0.21674443f, 0.11128102f, 0.03663285f};

// ---------------- helpers ----------------
__device__ __forceinline__ unsigned f2tf(float f) {
    unsigned r; asm("cvt.rna.tf32.f32 %0, %1;" : "=r"(r) : "f"(f)); return r;
}
__device__ __forceinline__ void mma8(float* d, const unsigned* a, const unsigned* b) {
    asm volatile("mma.sync.aligned.m16n8k8.row.col.f32.tf32.tf32.f32 "
        "{%0,%1,%2,%3}, {%4,%5,%6,%7}, {%8,%9}, {%0,%1,%2,%3};\n"
        : "+f"(d[0]), "+f"(d[1]), "+f"(d[2]), "+f"(d[3])
        : "r"(a[0]), "r"(a[1]), "r"(a[2]), "r"(a[3]), "r"(b[0]), "r"(b[1]));
}
__device__ __forceinline__ ull pk2(float lo, float hi) {
    ull r; asm("mov.b64 %0, {%1, %2};" : "=l"(r) : "f"(lo), "f"(hi)); return r;
}
__device__ __forceinline__ void fma2(ull& d, ull a, ull b) {
    asm("fma.rn.f32x2 %0, %1, %2, %0;" : "+l"(d) : "l"(a), "l"(b));
}
__device__ __forceinline__ ull add2(ull a, ull b) {
    ull r; asm("add.rn.f32x2 %0, %1, %2;" : "=l"(r) : "l"(a), "l"(b)); return r;
}

// ---------------- weight prep: OIHW -> [k9][CINP][COUT], tf32-rounded ------
__global__ void prep_w_kernel(const float* __restrict__ w, float* __restrict__ wp,
                              int COUT, int CIN, int CINP)
{
    int idx = blockIdx.x*256 + threadIdx.x;
    int total = 9*CINP*COUT;
    if (idx >= total) return;
    int co = idx % COUT;
    int t  = idx / COUT;
    int ci = t % CINP;
    int k9 = t / CINP;
    float v = (ci < CIN) ? w[((size_t)(co*CIN + ci))*9 + k9] : 0.f;
    wp[idx] = __uint_as_float(f2tf(v));
}

// ---------------- tf32 tensor-core 3x3 conv -------------------------------
// CTA = 256 threads, computes 128-pixel row strip x COUT channels.
// B (k=ci, n=pixel) from NCHW rows y-DIL,y,y+DIL in smem; A = weights in smem.
#define KC 16
#define PWD 136   // padded smem row width (136 % 32 == 8 -> conflict-free)

template<int COUT, int CIN, int DIL>
__global__ __launch_bounds__(256)
void conv_mma(const float* __restrict__ in, int CinS, int cinOff,
              const float* __restrict__ wp, const float* __restrict__ bias,
              float* __restrict__ out, int CoutS, int coutOff)
{
    constexpr int WM = (COUT >= 32) ? 32 : COUT;
    constexpr int NMW = COUT / WM;
    constexpr int NNW = 8 / NMW;
    constexpr int WN  = 128 / NNW;
    constexpr int MTILES = WM / 16;
    constexpr int NTILES = WN / 8;
    constexpr int CP  = COUT + 8;
    constexpr int PWU = 128 + 2*DIL;

    extern __shared__ __align__(16) unsigned smem_u[];
    unsigned* s_in = smem_u;                    // [3][KC][PWD]
    unsigned* s_w  = smem_u + 3*KC*PWD;         // [9][KC][CP]

    const int tid = threadIdx.x;
    const int x0  = blockIdx.x * 128;
    const int y   = blockIdx.y;
    const int bz  = blockIdx.z;
    const int wid = tid >> 5, lane = tid & 31;
    const int g = lane >> 2, c = lane & 3;
    const int wm = wid % NMW, wn = wid / NMW;

    float acc[MTILES][NTILES][4];
#pragma unroll
    for (int mt=0; mt<MTILES; mt++)
#pragma unroll
        for (int nt=0; nt<NTILES; nt++)
#pragma unroll
            for (int r=0; r<4; r++) acc[mt][nt][r] = 0.f;

#pragma unroll 1
    for (int ci0 = 0; ci0 < CIN; ci0 += KC) {
        __syncthreads();
        // fill input strip (3 rows x KC ch x PWU px), zero pad at borders
        {
            constexpr int FILLN = 3*KC*PWU;
            for (int idx = tid; idx < FILLN; idx += 256) {
                int px  = idx % PWU;
                int t   = idx / PWU;
                int ci  = t % KC;
                int row = t / KC;
                int gy = y + (row-1)*DIL;
                int gx = x0 - DIL + px;
                float v = 0.f;
                if (gy >= 0 && gy < HH && gx >= 0 && gx < WW)
                    v = in[((size_t)(bz*CinS + cinOff + ci0 + ci))*HWSZ + (size_t)gy*WW + gx];
                s_in[(row*KC + ci)*PWD + px] = f2tf(v);
            }
        }
        // fill weights [9][KC][CP]
        {
            constexpr int NW4 = 9*KC*(COUT/4);
            const float4* wp4base = (const float4*)wp;
            for (int idx = tid; idx < NW4; idx += 256) {
                int co4 = idx % (COUT/4);
                int t   = idx / (COUT/4);
                int ci  = t % KC;
                int k9  = t / KC;
                float4 v = wp4base[((size_t)(k9*CIN + ci0 + ci))*(COUT/4) + co4];
                *(float4*)((float*)s_w + (k9*KC + ci)*CP + co4*4) = v;
            }
        }
        __syncthreads();

#pragma unroll
        for (int ky=0; ky<3; ky++) {
#pragma unroll
            for (int kx=0; kx<3; kx++) {
                const int xoff = kx*DIL + wn*WN;
#pragma unroll
                for (int ks=0; ks<KC/8; ks++) {
                    unsigned a[MTILES][4];
#pragma unroll
                    for (int mt=0; mt<MTILES; mt++) {
                        const unsigned* wb = s_w + ((ky*3+kx)*KC + ks*8 + c)*CP + wm*WM + mt*16 + g;
                        a[mt][0] = wb[0];
                        a[mt][1] = wb[8];
                        a[mt][2] = wb[4*CP];
                        a[mt][3] = wb[4*CP + 8];
                    }
#pragma unroll
                    for (int nt=0; nt<NTILES; nt++) {
                        const unsigned* bb = s_in + (ky*KC + ks*8 + c)*PWD + xoff + nt*8 + g;
                        unsigned bv[2];
                        bv[0] = bb[0];
                        bv[1] = bb[4*PWD];
#pragma unroll
                        for (int mt=0; mt<MTILES; mt++)
                            mma8(acc[mt][nt], a[mt], bv);
                    }
                }
            }
        }
    }

    // epilogue -> NCHW
#pragma unroll
    for (int mt=0; mt<MTILES; mt++) {
        const int co0 = wm*WM + mt*16 + g;
        const float b0v = bias ? bias[co0]     : 0.f;
        const float b1v = bias ? bias[co0 + 8] : 0.f;
        float* o0 = out + ((size_t)(bz*CoutS + coutOff + co0))*HWSZ + (size_t)y*WW + x0 + wn*WN;
        float* o1 = o0 + (size_t)8*HWSZ;
#pragma unroll
        for (int nt=0; nt<NTILES; nt++) {
            const int px = nt*8 + 2*c;
            float2 v0; v0.x = acc[mt][nt][0] + b0v; v0.y = acc[mt][nt][1] + b0v;
            float2 v1; v1.x = acc[mt][nt][2] + b1v; v1.y = acc[mt][nt][3] + b1v;
            *(float2*)(o0 + px) = v0;
            *(float2*)(o1 + px) = v1;
        }
    }
}

// ---------------- tiny FFMA2 conv for the 16->2 head -----------------------
#define C_NT 128
#define C_TH 16
#define C_TW 64
#define C_CO 8

template<int DIL>
__global__ __launch_bounds__(C_NT, 3)
void conv3x3_kernel(const float* __restrict__ in, int Cin, int CinS, int cinOff,
                    const float* __restrict__ wgt, const float* __restrict__ bias,
                    float* __restrict__ out, int Cout, int CoutS, int coutOff)
{
    constexpr int TLW = C_TW + 2*DIL;
    constexpr int TLH = C_TH + 2*DIL;
    constexpr int NE  = (DIL==1) ? 5 : (DIL==2) ? 6 : 8;
    __shared__ __align__(16) float s_in[2][TLH*TLW];
    __shared__ __align__(16) ull   s_w2[2][C_CO*9];

    const int cb   = blockIdx.x * C_CO;
    const int tile = blockIdx.y;
    const int x0g  = (tile & 3) * C_TW;
    const int y0g  = (tile >> 2) * C_TH;
    const int b    = blockIdx.z;
    const int tid  = threadIdx.x;
    const int ty   = tid >> 3;
    const int xo   = (tid & 7) * 8;

    ull acc[C_CO][4];
#pragma unroll
    for (int co=0;co<C_CO;co++)
#pragma unroll
        for (int p=0;p<4;p++) acc[co][p] = 0ull;

    for (int ci0 = 0; ci0 < Cin; ci0 += 2) {
#pragma unroll
        for (int cc = 0; cc < 2; cc++) {
            const int ci = ci0 + cc;
            const float* ip = in + ((size_t)(b*CinS + cinOff + ci))*HWSZ;
            const bool cv = (ci < Cin);
            for (int idx = tid; idx < TLH*TLW; idx += C_NT) {
                int r = idx / TLW, cx = idx - r*TLW;
                int gy = y0g + r - DIL, gx = x0g + cx - DIL;
                float v = 0.f;
                if (cv && gy >= 0 && gy < HH && gx >= 0 && gx < WW) v = ip[gy*WW + gx];
                s_in[cc][idx] = v;
            }
        }
        for (int idx = tid; idx < 2*C_CO*9; idx += C_NT) {
            int cc = idx / (C_CO*9);
            int t  = idx - cc*(C_CO*9);
            int co = t / 9, k = t - co*9;
            int gci = ci0 + cc, gco = cb + co;
            float w = (gci < Cin && gco < Cout) ? wgt[((size_t)gco*Cin + gci)*9 + k] : 0.f;
            s_w2[cc][t] = pk2(w, w);
        }
        __syncthreads();
#pragma unroll
        for (int cc = 0; cc < 2; cc++) {
#pragma unroll
            for (int ky = 0; ky < 3; ky++) {
                const float* rowp = &s_in[cc][(ty + ky*DIL)*TLW + xo];
                ull E[NE];
#pragma unroll
                for (int i = 0; i < NE; i++) E[i] = *(const ull*)(rowp + 2*i);
                ull O[4];
                if (DIL == 1) {
#pragma unroll
                    for (int i = 0; i < 4; i++) O[i] = pk2(rowp[2*i+1], rowp[2*i+2]);
                }
#pragma unroll
                for (int kx = 0; kx < 3; kx++) {
                    ull vv[4];
                    if (DIL == 1) {
                        if (kx == 0)      { vv[0]=E[0]; vv[1]=E[1]; vv[2]=E[2]; vv[3]=E[3]; }
                        else if (kx == 1) { vv[0]=O[0]; vv[1]=O[1]; vv[2]=O[2]; vv[3]=O[3]; }
                        else              { vv[0]=E[1]; vv[1]=E[2]; vv[2]=E[3]; vv[3]=E[4]; }
                    } else {
                        const int base = kx*(DIL/2);
#pragma unroll
                        for (int p = 0; p < 4; p++) vv[p] = E[base + p];
                    }
#pragma unroll
                    for (int co = 0; co < C_CO; co++) {
                        ull w = s_w2[cc][co*9 + ky*3 + kx];
#pragma unroll
                        for (int p = 0; p < 4; p++) fma2(acc[co][p], w, vv[p]);
                    }
                }
            }
        }
        __syncthreads();
    }
#pragma unroll
    for (int co = 0; co < C_CO; co++) {
        int gco = cb + co;
        if (gco >= Cout) break;
        float bv = bias ? bias[gco] : 0.f;
        ull bv2 = pk2(bv, bv);
        float* op = out + ((size_t)(b*CoutS + coutOff + gco))*HWSZ + (y0g + ty)*WW + x0g + xo;
#pragma unroll
        for (int p = 0; p < 4; p++) {
            ull r = add2(acc[co][p], bv2);
            *(ull*)(op + 2*p) = r;
        }
    }
}

// ---------------- instance norm + leaky relu (in place, float4) ----------
__global__ void instnorm_lrelu_kernel(float* __restrict__ x, const float* __restrict__ gamma,
                                      const float* __restrict__ beta, int C)
{
    const int bc = blockIdx.x;
    float4* p = (float4*)(x + (size_t)bc*HWSZ);
    const int N4 = HWSZ/4;
    const int tid = threadIdx.x;
    float s = 0.f, s2 = 0.f;
    for (int i = tid; i < N4; i += 256) {
        float4 v = p[i];
        s  += v.x + v.y + v.z + v.w;
        s2 += v.x*v.x + v.y*v.y + v.z*v.z + v.w*v.w;
    }
    __shared__ float rs[256], rq[256];
    rs[tid] = s; rq[tid] = s2; __syncthreads();
    for (int off = 128; off > 0; off >>= 1) {
        if (tid < off) { rs[tid] += rs[tid+off]; rq[tid] += rq[tid+off]; }
        __syncthreads();
    }
    const float mu  = rs[0]*(1.f/HWSZ);
    const float var = rq[0]*(1.f/HWSZ) - mu*mu;
    const float inv = rsqrtf(var + 1e-5f);
    const int c = bc % C;
    const float ga = gamma[c]*inv, be = beta[c];
    for (int i = tid; i < N4; i += 256) {
        float4 v = p[i];
        v.x = (v.x-mu)*ga + be; v.x = (v.x >= 0.f) ? v.x : 0.2f*v.x;
        v.y = (v.y-mu)*ga + be; v.y = (v.y >= 0.f) ? v.y : 0.2f*v.y;
        v.z = (v.z-mu)*ga + be; v.z = (v.z >= 0.f) ? v.z : 0.2f*v.z;
        v.w = (v.w-mu)*ga + be; v.w = (v.w >= 0.f) ? v.w : 0.2f*v.w;
        p[i] = v;
    }
}

// ---------------- separable gaussian blur, replicate padding ------------
__global__ void blur_h_kernel(const float* __restrict__ in, int CinS, int cinOff,
                              float* __restrict__ out, int C, int n)
{
    int idx = blockIdx.x*blockDim.x + threadIdx.x;
    if (idx >= n) return;
    int x = idx % WW;
    int y = (idx / WW) % HH;
    int bc = idx / HWSZ;
    int b = bc / C, c = bc % C;
    const float* ip = in + ((size_t)(b*CinS + cinOff + c))*HWSZ + y*WW;
    float s = 0.f;
#pragma unroll
    for (int t = 0; t < 7; t++) {
        int xx = x + t - 3;
        xx = min(max(xx, 0), WW-1);
        s += GK[t]*ip[xx];
    }
    out[(size_t)bc*HWSZ + y*WW + x] = s;
}

__global__ void blur_v_kernel(const float* __restrict__ in, float* __restrict__ out, int n)
{
    int idx = blockIdx.x*blockDim.x + threadIdx.x;
    if (idx >= n) return;
    int x = idx % WW;
    int y = (idx / WW) % HH;
    int bc = idx / HWSZ;
    const float* ip = in + (size_t)bc*HWSZ;
    float s = 0.f;
#pragma unroll
    for (int t = 0; t < 7; t++) {
        int yy = y + t - 3;
        yy = min(max(yy, 0), HH-1);
        s += GK[t]*ip[yy*WW + x];
    }
    out[(size_t)bc*HWSZ + y*WW + x] = s;
}

// ---------------- local correlation ----------------
__global__ void corr_kernel(const float* __restrict__ f1s, const float* __restrict__ f2base,
                            float* __restrict__ out, float* __restrict__ lcsum)
{
    __shared__ float s1[22*22];
    __shared__ float red[256];
    const int bx = blockIdx.x, by = blockIdx.y, b = blockIdx.z;
    const int tid = threadIdx.x;
    const int ty = tid >> 4, tx = tid & 15;
    const int gy = by*16 + ty, gx = bx*16 + tx;

    float acc[49];
#pragma unroll
    for (int k = 0; k < 49; k++) acc[k] = 0.f;

    for (int c = 0; c < 64; c++) {
        const float* p1 = f1s    + ((size_t)(b*64  + c))*HWSZ;
        const float* p2 = f2base + ((size_t)(b*128 + 64 + c))*HWSZ;
        for (int idx = tid; idx < 22*22; idx += 256) {
            int r = idx/22, cc = idx%22;
            int yy = by*16 + r - 3, xx = bx*16 + cc - 3;
            s1[idx] = (yy >= 0 && yy < HH && xx >= 0 && xx < WW) ? p1[yy*WW+xx] : 0.f;
        }
        __syncthreads();
        const float v2 = p2[gy*WW + gx];
#pragma unroll
        for (int i = 0; i < 7; i++) {
#pragma unroll
            for (int j = 0; j < 7; j++) {
                float d = v2 - s1[(ty+i)*22 + tx+j];
                acc[i*7+j] += d*d;
            }
        }
        __syncthreads();
    }
    float tsum = 0.f;
#pragma unroll
    for (int k = 0; k < 49; k++) {
        float lc = acc[k]*(1.f/64.f);
        out[((size_t)(b*128 + 64 + k))*HWSZ + gy*WW + gx] = lc;
        tsum += lc;
    }
    red[tid] = tsum; __syncthreads();
    for (int off = 128; off > 0; off >>= 1) {
        if (tid < off) red[tid] += red[tid+off];
        __syncthreads();
    }
    if (tid == 0) atomicAdd(&lcsum[b], red[0]);
}

__global__ void zero_lcsum_kernel(float* lcsum)
{
    if (threadIdx.x < BB) lcsum[threadIdx.x] = 0.f;
}

__global__ void lcnorm_kernel(float* __restrict__ corr, const float* __restrict__ lcsum, int n)
{
    int idx = blockIdx.x*blockDim.x + threadIdx.x;
    if (idx >= n) return;
    int b = idx / (49*HWSZ);
    int r = idx - b*(49*HWSZ);
    float mean = lcsum[b]*(1.f/(49.f*HWSZ));
    float s = 1.f/(mean + 1e-6f);
    corr[((size_t)b*128 + 64)*HWSZ + r] *= s;
}

// ---------------- host side ----------------
template<int COUT, int CIN, int DIL>
static void launch_mma(const float* in, int CinS, int cinOff,
                       const float* wp, const float* bias,
                       float* out, int CoutS, int coutOff)
{
    const int smem = (3*KC*PWD + 9*KC*(COUT+8))*4;
    cudaFuncSetAttribute(conv_mma<COUT,CIN,DIL>,
                         cudaFuncAttributeMaxDynamicSharedMemorySize, smem);
    conv_mma<COUT,CIN,DIL><<<dim3(2, HH, BB), 256, smem>>>(
        in, CinS, cinOff, wp, bias, out, CoutS, coutOff);
}

extern "C" void kernel_launch(void* const* d_in, const int* in_sizes, int n_in,
                              void* d_out, int out_size)
{
    const float* feat1  = (const float*)d_in[0];
    const float* feat2  = (const float*)d_in[1];
    const float* pre_w  = (const float*)d_in[2];
    const float* pre_b  = (const float*)d_in[3];
    const float* fc1_w  = (const float*)d_in[4];
    const float* fc1_g  = (const float*)d_in[5];
    const float* fc1_be = (const float*)d_in[6];
    const float* fc2_w  = (const float*)d_in[7];
    const float* fc2_b  = (const float*)d_in[8];
    const float* e1_w   = (const float*)d_in[9];
    const float* e1_g   = (const float*)d_in[10];
    const float* e1_be  = (const float*)d_in[11];
    const float* e2_w   = (const float*)d_in[12];
    const float* e2_g   = (const float*)d_in[13];
    const float* e2_be  = (const float*)d_in[14];
    const float* e3_w   = (const float*)d_in[15];
    const float* e3_g   = (const float*)d_in[16];
    const float* e3_be  = (const float*)d_in[17];
    const float* head_w = (const float*)d_in[18];
    const float* head_b = (const float*)d_in[19];
    float* out = (float*)d_out;

    float *cat_, *x128, *corr_, *f1s, *tmp_, *x64, *x32, *x16, *head_, *lcsum, *wpb;
    cudaGetSymbolAddress((void**)&cat_,  g_cat);
    cudaGetSymbolAddress((void**)&x128,  g_x128);
    cudaGetSymbolAddress((void**)&corr_, g_corr);
    cudaGetSymbolAddress((void**)&f1s,   g_f1s);
    cudaGetSymbolAddress((void**)&tmp_,  g_tmp);
    cudaGetSymbolAddress((void**)&x64,   g_x64);
    cudaGetSymbolAddress((void**)&x32,   g_x32);
    cudaGetSymbolAddress((void**)&x16,   g_x16);
    cudaGetSymbolAddress((void**)&head_, g_head);
    cudaGetSymbolAddress((void**)&lcsum, g_lcsum);
    cudaGetSymbolAddress((void**)&wpb,   g_wp);

    float* wp_pre = wpb;
    float* wp_fc1 = wpb + 36864;
    float* wp_fc2 = wpb + 184320;
    float* wp_e1  = wpb + 258048;
    float* wp_e2  = wpb + 331776;
    float* wp_e3  = wpb + 350208;

    // weight prep (reorder + tf32 round + ci pad)
    prep_w_kernel<<<(9*64*64   + 255)/256, 256>>>(pre_w, wp_pre, 64, 64, 64);
    prep_w_kernel<<<(9*128*128 + 255)/256, 256>>>(fc1_w, wp_fc1, 128, 128, 128);
    prep_w_kernel<<<(9*128*64  + 255)/256, 256>>>(fc2_w, wp_fc2, 64, 128, 128);
    prep_w_kernel<<<(9*128*64  + 255)/256, 256>>>(e1_w,  wp_e1,  64, 113, 128);
    prep_w_kernel<<<(9*64*32   + 255)/256, 256>>>(e2_w,  wp_e2,  32, 64, 64);
    prep_w_kernel<<<(9*32*16   + 255)/256, 256>>>(e3_w,  wp_e3,  16, 32, 32);

    // preprocessor (shared weights) -> concat buffer
    launch_mma<64,64,1>(feat1, 64, 0, wp_pre, pre_b, cat_, 128, 0);
    launch_mma<64,64,1>(feat2, 64, 0, wp_pre, pre_b, cat_, 128, 64);

    // featcompressor layer1 + IN + lrelu
    launch_mma<128,128,1>(cat_, 128, 0, wp_fc1, nullptr, x128, 128, 0);
    instnorm_lrelu_kernel<<<BB*128, 256>>>(x128, fc1_g, fc1_be, 128);

    // featcompressor layer2 -> corr channels 0..63
    launch_mma<64,128,1>(x128, 128, 0, wp_fc2, fc2_b, corr_, 128, 0);

    // gaussian blur of f1 (replicate pad, separable)
    {
        int n = BB*64*HWSZ;
        blur_h_kernel<<<(n+255)/256, 256>>>(cat_, 128, 0, tmp_, 64, n);
        blur_v_kernel<<<(n+255)/256, 256>>>(tmp_, f1s, n);
    }

    // local correlation -> corr channels 64..112, then normalize by batch mean
    zero_lcsum_kernel<<<1, 32>>>(lcsum);
    corr_kernel<<<dim3(WW/16, HH/16, BB), 256>>>(f1s, cat_, corr_, lcsum);
    {
        int n = BB*49*HWSZ;
        lcnorm_kernel<<<(n+255)/256, 256>>>(corr_, lcsum, n);
    }

    // estimator stack (e1 reads 128-ch corr; weights zero-padded for ci>=113)
    launch_mma<64,128,1>(corr_, 128, 0, wp_e1, nullptr, x64, 64, 0);
    instnorm_lrelu_kernel<<<BB*64, 256>>>(x64, e1_g, e1_be, 64);

    launch_mma<32,64,2>(x64, 64, 0, wp_e2, nullptr, x32, 32, 0);
    instnorm_lrelu_kernel<<<BB*32, 256>>>(x32, e2_g, e2_be, 32);

    launch_mma<16,32,4>(x32, 32, 0, wp_e3, nullptr, x16, 16, 0);
    instnorm_lrelu_kernel<<<BB*16, 256>>>(x16, e3_g, e3_be, 16);

    // flow head (tiny, FFMA2 direct conv)
    {
        dim3 grid(1, (WW/C_TW)*(HH/C_TH), BB);
        conv3x3_kernel<1><<<grid, C_NT>>>(x16, 16, 16, 0, head_w, head_b, head_, 2, 2, 0);
    }

    // final blur -> output
    {
        int n = BB*2*HWSZ;
        blur_h_kernel<<<(n+255)/256, 256>>>(head_, 2, 0, tmp_, 2, n);
        blur_v_kernel<<<(n+255)/256, 256>>>(tmp_, out, n);
    }
}